// round 14
// baseline (speedup 1.0000x reference)
#include <cuda_runtime.h>
#include <cuda_bf16.h>

#define D_DIM   512
#define H1_DIM  128
#define H2_DIM  64
#define B_DIM   2048
#define N_NODES 20000
#define N_DRUG  2000

typedef unsigned long long ull;

__device__ __forceinline__ unsigned smem_u32(const void* p) {
    unsigned a;
    asm("{ .reg .u64 t; cvta.to.shared.u64 t, %1; cvt.u32.u64 %0, t; }" : "=r"(a) : "l"(p));
    return a;
}

#define SW128(o) ((o) ^ ((((o) >> 3) & 0x70)))

// Scratch.  g_Pbot rows [0,2000) = dense Pbot (neg1); rows [2000,4048) = P_t[b].
__device__ float g_Ptop[N_DRUG * H1_DIM];
__device__ float g_Pbot[4096 * H1_DIM];
__device__ __nv_bfloat16 g_Wthi[H1_DIM * 1024];
__device__ __nv_bfloat16 g_Wtlo[H1_DIM * 1024];
__device__ __nv_bfloat16 g_W2thi[H2_DIM * H1_DIM];
__device__ __nv_bfloat16 g_W2tlo[H2_DIM * H1_DIM];

// ---------------------------------------------------------------------------
// Kernel 0a/0b: weight conversion (validated)
// ---------------------------------------------------------------------------
__global__ void __launch_bounds__(256) convert_w1_kernel(const float* __restrict__ W1) {
    __shared__ unsigned short s_hi[128][34];
    __shared__ unsigned short s_lo[128][34];
    const int tid = threadIdx.x;
    const int k0 = blockIdx.x * 32;
#pragma unroll
    for (int it = 0; it < 16; it++) {
        int idx = it * 256 + tid;
        int kk = idx >> 7;
        int n  = idx & 127;
        float x = W1[(k0 + kk) * H1_DIM + n];
        __nv_bfloat16 hb = __float2bfloat16(x);
        float hf = __bfloat162float(hb);
        __nv_bfloat16 lb = __float2bfloat16(x - hf);
        s_hi[n][kk] = __bfloat16_as_ushort(hb);
        s_lo[n][kk] = __bfloat16_as_ushort(lb);
    }
    __syncthreads();
#pragma unroll
    for (int it = 0; it < 16; it++) {
        int idx = it * 256 + tid;
        int n  = idx >> 5;
        int kk = idx & 31;
        g_Wthi[n * 1024 + k0 + kk] = __ushort_as_bfloat16(s_hi[n][kk]);
        g_Wtlo[n * 1024 + k0 + kk] = __ushort_as_bfloat16(s_lo[n][kk]);
    }
}

__global__ void __launch_bounds__(256) convert_w2_kernel(const float* __restrict__ W2) {
    int idx = blockIdx.x * 256 + threadIdx.x;
    int k = idx >> 6;
    int n = idx & 63;
    float x = W2[k * H2_DIM + n];
    __nv_bfloat16 hb = __float2bfloat16(x);
    float hf = __bfloat162float(hb);
    g_W2thi[n * H1_DIM + k] = hb;
    g_W2tlo[n * H1_DIM + k] = __float2bfloat16(x - hf);
}

// ---------------------------------------------------------------------------
// HMMA helpers (validated)
// ---------------------------------------------------------------------------
__device__ __forceinline__ void ldm_x4(unsigned addr, unsigned& r0, unsigned& r1,
                                       unsigned& r2, unsigned& r3) {
    asm volatile("ldmatrix.sync.aligned.m8n8.x4.shared.b16 {%0,%1,%2,%3}, [%4];"
                 : "=r"(r0), "=r"(r1), "=r"(r2), "=r"(r3) : "r"(addr));
}
__device__ __forceinline__ void mma_bf16(float* c, unsigned a0, unsigned a1,
                                         unsigned a2, unsigned a3,
                                         unsigned b0, unsigned b1) {
    asm volatile("mma.sync.aligned.m16n8k16.row.col.f32.bf16.bf16.f32 "
                 "{%0,%1,%2,%3}, {%4,%5,%6,%7}, {%8,%9}, {%0,%1,%2,%3};"
                 : "+f"(c[0]), "+f"(c[1]), "+f"(c[2]), "+f"(c[3])
                 : "r"(a0), "r"(a1), "r"(a2), "r"(a3), "r"(b0), "r"(b1));
}
__device__ __forceinline__ unsigned amat_addr(unsigned base, int m0, int k0, int lane) {
    unsigned off = (unsigned)((m0 + (lane & 15)) * 128 + ((k0 >> 3) + (lane >> 4)) * 16);
    return base + SW128(off);
}
__device__ __forceinline__ unsigned bmat_addr(unsigned base, int n0, int k0, int lane) {
    unsigned off = (unsigned)((n0 + (lane & 7) + ((lane >> 4) << 3)) * 128
                            + ((k0 >> 3) + ((lane >> 3) & 1)) * 16);
    return base + SW128(off);
}
__device__ __forceinline__ void split4(float4 v, unsigned& hi01, unsigned& hi23,
                                       unsigned& lo01, unsigned& lo23) {
    asm("cvt.rn.bf16x2.f32 %0, %1, %2;" : "=r"(hi01) : "f"(v.y), "f"(v.x));
    asm("cvt.rn.bf16x2.f32 %0, %1, %2;" : "=r"(hi23) : "f"(v.w), "f"(v.z));
    float h0 = __uint_as_float(hi01 << 16);
    float h1 = __uint_as_float(hi01 & 0xffff0000u);
    float h2 = __uint_as_float(hi23 << 16);
    float h3 = __uint_as_float(hi23 & 0xffff0000u);
    asm("cvt.rn.bf16x2.f32 %0, %1, %2;" : "=r"(lo01) : "f"(v.y - h1), "f"(v.x - h0));
    asm("cvt.rn.bf16x2.f32 %0, %1, %2;" : "=r"(lo23) : "f"(v.w - h3), "f"(v.z - h2));
}

// ---------------------------------------------------------------------------
// Kernel 1 v5: R13 row set + 256 threads + DOUBLE-BUFFERED smem with register
// prefetch: chunk c+1's LDGs issue before chunk c's compute; split+STS after.
// One barrier per chunk. smem 64KB dynamic -> 3 blocks/SM possible.
// ---------------------------------------------------------------------------
#define G1_GRID 192
#define G1_SMEM 65536

__global__ void __launch_bounds__(256) gemm1_mma_kernel(const float* __restrict__ embed,
                                                        const int* __restrict__ t) {
    extern __shared__ char sm[];
    __shared__ int t_s[64];
    const unsigned sb = smem_u32(sm);
    const int tid = threadIdx.x;
    const int wid = tid >> 5;
    const int lane = tid & 31;

    int bx = blockIdx.x;
    const int nh = bx & 1;
    int bt = bx >> 1;
    int woff, row0, M;
    float* P;
    bool gat = false;
    if (bt < 32)      { woff = 0;     P = g_Ptop; row0 = bt * 64;        M = N_DRUG; }
    else if (bt < 64) { woff = D_DIM; P = g_Pbot; row0 = (bt - 32) * 64; M = N_DRUG; }
    else { woff = D_DIM; P = g_Pbot + 2000 * H1_DIM; row0 = (bt - 64) * 64; M = B_DIM; gat = true; }
    const int n0 = nh * 64;

    if (gat && tid < 64) t_s[tid] = t[row0 + tid];
    __syncthreads();

    const int wr = wid >> 1;
    const int wc = wid & 1;
    const int m0 = wr * 16;
    const int nbw = wc * 32;

    // per-thread staging coords
    const int arow = tid >> 2;              // 0..63 (A row)
    const int acol = (tid & 3) << 4;        // 0,16,32,48 (A col base)
    const int ag = gat ? t_s[arow] : min(row0 + arow, N_DRUG - 1);
    const float* aptr = embed + (size_t)ag * D_DIM + acol;
    const int brow = tid >> 2;              // 0..63 (B row = n)
    const int bcol = (tid & 3) << 4;        // k base; 4 uint2 groups of 4
    const __nv_bfloat16* bhp = g_Wthi + (n0 + brow) * 1024 + woff + bcol;
    const __nv_bfloat16* blp = g_Wtlo + (n0 + brow) * 1024 + woff + bcol;

    float4 av[4];
    uint2 bhv[4], blv[4];

    float acc[4][4];
#pragma unroll
    for (int i = 0; i < 4; i++)
#pragma unroll
        for (int q = 0; q < 4; q++) acc[i][q] = 0.f;

    // prologue: load + stage chunk 0 into buf 0
#pragma unroll
    for (int g = 0; g < 4; g++) {
        av[g]  = *(const float4*)(aptr + g * 4);
        bhv[g] = *(const uint2*)(bhp + g * 4);
        blv[g] = *(const uint2*)(blp + g * 4);
    }
#pragma unroll
    for (int g = 0; g < 4; g++) {
        unsigned hi01, hi23, lo01, lo23;
        split4(av[g], hi01, hi23, lo01, lo23);
        unsigned aoff = SW128((unsigned)(arow * 128 + (acol + g * 4) * 2));
        *(uint2*)(sm + 0    + aoff) = make_uint2(hi01, hi23);   // AHI
        *(uint2*)(sm + 8192 + aoff) = make_uint2(lo01, lo23);   // ALO
        unsigned boff = SW128((unsigned)(brow * 128 + (bcol + g * 4) * 2));
        *(uint2*)(sm + 16384 + boff) = bhv[g];                  // BHI
        *(uint2*)(sm + 24576 + boff) = blv[g];                  // BLO
    }
    __syncthreads();

    for (int c = 0; c < 8; c++) {
        const unsigned cb = (unsigned)((c & 1) * 32768);
        const unsigned nb2 = (unsigned)(((c + 1) & 1) * 32768);
        if (c < 7) {   // issue next chunk's LDGs now (overlap with compute)
            const int kb = (c + 1) * 64;
#pragma unroll
            for (int g = 0; g < 4; g++) {
                av[g]  = *(const float4*)(aptr + kb + g * 4);
                bhv[g] = *(const uint2*)(bhp + kb + g * 4);
                blv[g] = *(const uint2*)(blp + kb + g * 4);
            }
        }
        // ---- compute chunk c ----
#pragma unroll
        for (int ks = 0; ks < 4; ks++) {
            const int k0 = ks * 16;
            unsigned bh[4][2], bl[4][2], t0, t1, t2, t3;
            ldm_x4(bmat_addr(sb + cb + 16384, nbw,      k0, lane), t0, t1, t2, t3);
            bh[0][0] = t0; bh[0][1] = t1; bh[1][0] = t2; bh[1][1] = t3;
            ldm_x4(bmat_addr(sb + cb + 16384, nbw + 16, k0, lane), t0, t1, t2, t3);
            bh[2][0] = t0; bh[2][1] = t1; bh[3][0] = t2; bh[3][1] = t3;
            ldm_x4(bmat_addr(sb + cb + 24576, nbw,      k0, lane), t0, t1, t2, t3);
            bl[0][0] = t0; bl[0][1] = t1; bl[1][0] = t2; bl[1][1] = t3;
            ldm_x4(bmat_addr(sb + cb + 24576, nbw + 16, k0, lane), t0, t1, t2, t3);
            bl[2][0] = t0; bl[2][1] = t1; bl[3][0] = t2; bl[3][1] = t3;
            unsigned ah0, ah1, ah2, ah3, al0, al1, al2, al3;
            ldm_x4(amat_addr(sb + cb + 0, m0, k0, lane), ah0, ah1, ah2, ah3);
            ldm_x4(amat_addr(sb + cb + 8192, m0, k0, lane), al0, al1, al2, al3);
#pragma unroll
            for (int nf = 0; nf < 4; nf++)
                mma_bf16(acc[nf], ah0, ah1, ah2, ah3, bh[nf][0], bh[nf][1]);
#pragma unroll
            for (int nf = 0; nf < 4; nf++)
                mma_bf16(acc[nf], ah0, ah1, ah2, ah3, bl[nf][0], bl[nf][1]);
#pragma unroll
            for (int nf = 0; nf < 4; nf++)
                mma_bf16(acc[nf], al0, al1, al2, al3, bh[nf][0], bh[nf][1]);
        }
        if (c < 7) {   // stage next chunk into the other buffer
#pragma unroll
            for (int g = 0; g < 4; g++) {
                unsigned hi01, hi23, lo01, lo23;
                split4(av[g], hi01, hi23, lo01, lo23);
                unsigned aoff = SW128((unsigned)(arow * 128 + (acol + g * 4) * 2));
                *(uint2*)(sm + nb2 + 0    + aoff) = make_uint2(hi01, hi23);
                *(uint2*)(sm + nb2 + 8192 + aoff) = make_uint2(lo01, lo23);
                unsigned boff = SW128((unsigned)(brow * 128 + (bcol + g * 4) * 2));
                *(uint2*)(sm + nb2 + 16384 + boff) = bhv[g];
                *(uint2*)(sm + nb2 + 24576 + boff) = blv[g];
            }
            __syncthreads();
        }
    }

    // ---- epilogue ----
#pragma unroll
    for (int nf = 0; nf < 4; nf++) {
        int r = row0 + m0 + (lane >> 2);
        int col = n0 + nbw + nf * 8 + 2 * (lane & 3);
        if (r < M)
            *(float2*)&P[(size_t)r * H1_DIM + col] = make_float2(acc[nf][0], acc[nf][1]);
        if (r + 8 < M)
            *(float2*)&P[(size_t)(r + 8) * H1_DIM + col] = make_float2(acc[nf][2], acc[nf][3]);
    }
}

// ---------------------------------------------------------------------------
// Kernel 2 v6: R12 all-warps design, 64 samples/block -> smem ~68KB ->
// 3 blocks/SM (cross-block phase overlap). Grid 2080.
// ---------------------------------------------------------------------------
#define M2_XHI 0                      // 2 chunks x 8KB
#define M2_XLO 16384
#define M2_WHI 32768                  // 2 chunks x 8KB
#define M2_WLO 49152
#define M2_MISC 65536
// misc: b1s[128], b2s[64], W3s[64], partial[128] floats + sTop/sBot/sOut[64] ints
#define M2_SMEM (M2_MISC + (128 + 64 + 64 + 128) * 4 + 3 * 64 * 4)

__global__ void __launch_bounds__(256, 3) mlp2_mma_kernel(
    const int* __restrict__ h, const int* __restrict__ t, const int* __restrict__ ns,
    const float* __restrict__ b1, const float* __restrict__ b2,
    const float* __restrict__ W3, const float* __restrict__ b3,
    float* __restrict__ out)
{
    extern __shared__ char sm[];
    const unsigned sb = smem_u32(sm);
    float* b1s     = (float*)(sm + M2_MISC);
    float* b2s     = b1s + 128;
    float* W3s     = b2s + 64;
    float* partial = W3s + 64;                 // [64 rows][2 halves]
    int* sTop = (int*)(partial + 128);
    int* sBot = sTop + 64;
    int* sOut = sBot + 64;

    const int tid = threadIdx.x;
    const int wid = tid >> 5;
    const int lane = tid & 31;

    // ---- phase 0: indices + small tensors ----
    if (tid < 64) {
        int S = blockIdx.x * 64 + tid;
        int b = S / 65;
        int r = S - b * 65;
        int itop, jbot, oaddr;
        if (r == 64)      { itop = h[b];           jbot = 2000 + b;       oaddr = b; }
        else if (r < 32)  { itop = h[b];           jbot = ns[b * 64 + r]; oaddr = B_DIM + b * 64 + r; }
        else              { itop = ns[b * 64 + r]; jbot = 2000 + b;       oaddr = B_DIM + b * 64 + r; }
        sTop[tid] = itop; sBot[tid] = jbot; sOut[tid] = oaddr;
    }
    if (tid < 128) b1s[tid] = b1[tid];
    if (tid < 64) { b2s[tid] = b2[tid]; W3s[tid] = W3[tid]; }
    // W2 tiles: 2048 uint2 over 256 threads
#pragma unroll
    for (int it = 0; it < 8; it++) {
        int idx = it * 256 + tid;
        int c = idx >> 10;
        int rem = idx & 1023;
        int n = rem >> 4;
        int kq = rem & 15;
        unsigned off = (unsigned)(c * 8192) + SW128((unsigned)(n * 128 + kq * 8));
        *(uint2*)(sm + M2_WHI + off) = *(const uint2*)&g_W2thi[n * H1_DIM + c * 64 + kq * 4];
        *(uint2*)(sm + M2_WLO + off) = *(const uint2*)&g_W2tlo[n * H1_DIM + c * 64 + kq * 4];
    }
    __syncthreads();

    // ---- phase 1: gather + split, one warp per sample (8 iters of 8 warps) ----
    {
        const int kcol = lane * 4;
        const int cch = lane >> 4;          // chunk 0/1
        const int kin = (lane & 15) * 4;
        const float4 vb = *(const float4*)&b1s[kcol];
#pragma unroll
        for (int it = 0; it < 8; it++) {
            int s = it * 8 + wid;
            const float* pt = g_Ptop + (size_t)sTop[s] * H1_DIM;
            const float* pb = g_Pbot + (size_t)sBot[s] * H1_DIM;
            float4 pa = *(const float4*)&pt[kcol];
            float4 pv = *(const float4*)&pb[kcol];
            float4 x;
            x.x = fmaxf(pa.x + pv.x + vb.x, 0.f);
            x.y = fmaxf(pa.y + pv.y + vb.y, 0.f);
            x.z = fmaxf(pa.z + pv.z + vb.z, 0.f);
            x.w = fmaxf(pa.w + pv.w + vb.w, 0.f);
            unsigned hi01, hi23, lo01, lo23;
            split4(x, hi01, hi23, lo01, lo23);
            unsigned off = (unsigned)(cch * 8192) + SW128((unsigned)(s * 128 + kin * 2));
            *(uint2*)(sm + M2_XHI + off) = make_uint2(hi01, hi23);
            *(uint2*)(sm + M2_XLO + off) = make_uint2(lo01, lo23);
        }
    }
    __syncthreads();

    // ---- phase 2: MMA. Warp tile 16m x 32n over 64x64 ----
    const int m0 = (wid >> 1) * 16;
    const int wn = wid & 1;
    const int nb = wn * 32;

    float acc[4][4];
#pragma unroll
    for (int j = 0; j < 4; j++)
#pragma unroll
        for (int q = 0; q < 4; q++) acc[j][q] = 0.f;

#pragma unroll
    for (int c = 0; c < 2; c++) {
        const unsigned xbhi = sb + M2_XHI + c * 8192;
        const unsigned xblo = sb + M2_XLO + c * 8192;
        const unsigned wbhi = sb + M2_WHI + c * 8192;
        const unsigned wblo = sb + M2_WLO + c * 8192;
#pragma unroll
        for (int ks = 0; ks < 4; ks++) {
            const int k0 = ks * 16;
            unsigned bh[4][2], bl[4][2], t0, t1, t2, t3;
            ldm_x4(bmat_addr(wbhi, nb,      k0, lane), t0, t1, t2, t3);
            bh[0][0] = t0; bh[0][1] = t1; bh[1][0] = t2; bh[1][1] = t3;
            ldm_x4(bmat_addr(wbhi, nb + 16, k0, lane), t0, t1, t2, t3);
            bh[2][0] = t0; bh[2][1] = t1; bh[3][0] = t2; bh[3][1] = t3;
            ldm_x4(bmat_addr(wblo, nb,      k0, lane), t0, t1, t2, t3);
            bl[0][0] = t0; bl[0][1] = t1; bl[1][0] = t2; bl[1][1] = t3;
            ldm_x4(bmat_addr(wblo, nb + 16, k0, lane), t0, t1, t2, t3);
            bl[2][0] = t0; bl[2][1] = t1; bl[3][0] = t2; bl[3][1] = t3;
            unsigned ah0, ah1, ah2, ah3, al0, al1, al2, al3;
            ldm_x4(amat_addr(xbhi, m0, k0, lane), ah0, ah1, ah2, ah3);
            ldm_x4(amat_addr(xblo, m0, k0, lane), al0, al1, al2, al3);
#pragma unroll
            for (int nf = 0; nf < 4; nf++)
                mma_bf16(acc[nf], ah0, ah1, ah2, ah3, bh[nf][0], bh[nf][1]);
#pragma unroll
            for (int nf = 0; nf < 4; nf++)
                mma_bf16(acc[nf], ah0, ah1, ah2, ah3, bl[nf][0], bl[nf][1]);
#pragma unroll
            for (int nf = 0; nf < 4; nf++)
                mma_bf16(acc[nf], al0, al1, al2, al3, bh[nf][0], bh[nf][1]);
        }
    }

    // ---- phase 3: relu(acc + b2) . W3, reduce ----
    {
        float p0 = 0.f, p8 = 0.f;
#pragma unroll
        for (int nf = 0; nf < 4; nf++) {
            int n0i = nb + nf * 8 + 2 * (lane & 3);
            float b20 = b2s[n0i], b21 = b2s[n0i + 1];
            float w30 = W3s[n0i], w31 = W3s[n0i + 1];
            p0 = fmaf(fmaxf(acc[nf][0] + b20, 0.f), w30, p0);
            p0 = fmaf(fmaxf(acc[nf][1] + b21, 0.f), w31, p0);
            p8 = fmaf(fmaxf(acc[nf][2] + b20, 0.f), w30, p8);
            p8 = fmaf(fmaxf(acc[nf][3] + b21, 0.f), w31, p8);
        }
        p0 += __shfl_xor_sync(0xffffffffu, p0, 1);
        p0 += __shfl_xor_sync(0xffffffffu, p0, 2);
        p8 += __shfl_xor_sync(0xffffffffu, p8, 1);
        p8 += __shfl_xor_sync(0xffffffffu, p8, 2);
        if ((lane & 3) == 0) {
            int r = m0 + (lane >> 2);
            partial[r * 2 + wn]       = p0;
            partial[(r + 8) * 2 + wn] = p8;
        }
    }
    __syncthreads();
    if (tid < 64)
        out[sOut[tid]] = partial[tid * 2] + partial[tid * 2 + 1] + b3[0];
}

// ---------------------------------------------------------------------------
extern "C" void kernel_launch(void* const* d_in, const int* in_sizes, int n_in,
                              void* d_out, int out_size) {
    const float* embed = (const float*)d_in[0];
    const float* W1    = (const float*)d_in[1];
    const float* b1    = (const float*)d_in[2];
    const float* W2    = (const float*)d_in[3];
    const float* b2    = (const float*)d_in[4];
    const float* W3    = (const float*)d_in[5];
    const float* b3    = (const float*)d_in[6];
    const int*   h     = (const int*)d_in[7];
    const int*   t     = (const int*)d_in[8];
    const int*   ns    = (const int*)d_in[9];
    float* out = (float*)d_out;

    convert_w1_kernel<<<32, 256>>>(W1);
    convert_w2_kernel<<<32, 256>>>(W2);

    cudaFuncSetAttribute(gemm1_mma_kernel, cudaFuncAttributeMaxDynamicSharedMemorySize,
                         G1_SMEM);
    gemm1_mma_kernel<<<G1_GRID, 256, G1_SMEM>>>(embed, t);

    cudaFuncSetAttribute(mlp2_mma_kernel, cudaFuncAttributeMaxDynamicSharedMemorySize,
                         M2_SMEM);
    mlp2_mma_kernel<<<(B_DIM * 65) / 64, 256, M2_SMEM>>>(h, t, ns, b1, b2, W3, b3, out);
}

// round 17
// speedup vs baseline: 1.0223x; 1.0223x over previous
#include <cuda_runtime.h>
#include <cuda_bf16.h>

#define D_DIM   512
#define H1_DIM  128
#define H2_DIM  64
#define B_DIM   2048
#define N_NODES 20000
#define N_DRUG  2000

typedef unsigned long long ull;

__device__ __forceinline__ unsigned smem_u32(const void* p) {
    unsigned a;
    asm("{ .reg .u64 t; cvta.to.shared.u64 t, %1; cvt.u32.u64 %0, t; }" : "=r"(a) : "l"(p));
    return a;
}

#define SW128(o) ((o) ^ ((((o) >> 3) & 0x70)))

// Scratch.  g_Pbot rows [0,2000) = dense Pbot (neg1); rows [2000,4048) = P_t[b].
__device__ float g_Ptop[N_DRUG * H1_DIM];
__device__ float g_Pbot[4096 * H1_DIM];
__device__ __nv_bfloat16 g_Wthi[H1_DIM * 1024];
__device__ __nv_bfloat16 g_Wtlo[H1_DIM * 1024];
__device__ __nv_bfloat16 g_W2thi[H2_DIM * H1_DIM];
__device__ __nv_bfloat16 g_W2tlo[H2_DIM * H1_DIM];

// ---------------------------------------------------------------------------
// Kernel 0a/0b: weight conversion (validated)
// ---------------------------------------------------------------------------
__global__ void __launch_bounds__(256) convert_w1_kernel(const float* __restrict__ W1) {
    __shared__ unsigned short s_hi[128][34];
    __shared__ unsigned short s_lo[128][34];
    const int tid = threadIdx.x;
    const int k0 = blockIdx.x * 32;
#pragma unroll
    for (int it = 0; it < 16; it++) {
        int idx = it * 256 + tid;
        int kk = idx >> 7;
        int n  = idx & 127;
        float x = W1[(k0 + kk) * H1_DIM + n];
        __nv_bfloat16 hb = __float2bfloat16(x);
        float hf = __bfloat162float(hb);
        __nv_bfloat16 lb = __float2bfloat16(x - hf);
        s_hi[n][kk] = __bfloat16_as_ushort(hb);
        s_lo[n][kk] = __bfloat16_as_ushort(lb);
    }
    __syncthreads();
#pragma unroll
    for (int it = 0; it < 16; it++) {
        int idx = it * 256 + tid;
        int n  = idx >> 5;
        int kk = idx & 31;
        g_Wthi[n * 1024 + k0 + kk] = __ushort_as_bfloat16(s_hi[n][kk]);
        g_Wtlo[n * 1024 + k0 + kk] = __ushort_as_bfloat16(s_lo[n][kk]);
    }
}

__global__ void __launch_bounds__(256) convert_w2_kernel(const float* __restrict__ W2) {
    int idx = blockIdx.x * 256 + threadIdx.x;
    int k = idx >> 6;
    int n = idx & 63;
    float x = W2[k * H2_DIM + n];
    __nv_bfloat16 hb = __float2bfloat16(x);
    float hf = __bfloat162float(hb);
    g_W2thi[n * H1_DIM + k] = hb;
    g_W2tlo[n * H1_DIM + k] = __float2bfloat16(x - hf);
}

// ---------------------------------------------------------------------------
// HMMA helpers (validated)
// ---------------------------------------------------------------------------
__device__ __forceinline__ void ldm_x4(unsigned addr, unsigned& r0, unsigned& r1,
                                       unsigned& r2, unsigned& r3) {
    asm volatile("ldmatrix.sync.aligned.m8n8.x4.shared.b16 {%0,%1,%2,%3}, [%4];"
                 : "=r"(r0), "=r"(r1), "=r"(r2), "=r"(r3) : "r"(addr));
}
__device__ __forceinline__ void mma_bf16(float* c, unsigned a0, unsigned a1,
                                         unsigned a2, unsigned a3,
                                         unsigned b0, unsigned b1) {
    asm volatile("mma.sync.aligned.m16n8k16.row.col.f32.bf16.bf16.f32 "
                 "{%0,%1,%2,%3}, {%4,%5,%6,%7}, {%8,%9}, {%0,%1,%2,%3};"
                 : "+f"(c[0]), "+f"(c[1]), "+f"(c[2]), "+f"(c[3])
                 : "r"(a0), "r"(a1), "r"(a2), "r"(a3), "r"(b0), "r"(b1));
}
__device__ __forceinline__ unsigned amat_addr(unsigned base, int m0, int k0, int lane) {
    unsigned off = (unsigned)((m0 + (lane & 15)) * 128 + ((k0 >> 3) + (lane >> 4)) * 16);
    return base + SW128(off);
}
__device__ __forceinline__ unsigned bmat_addr(unsigned base, int n0, int k0, int lane) {
    unsigned off = (unsigned)((n0 + (lane & 7) + ((lane >> 4) << 3)) * 128
                            + ((k0 >> 3) + ((lane >> 3) & 1)) * 16);
    return base + SW128(off);
}
__device__ __forceinline__ void split4(float4 v, unsigned& hi01, unsigned& hi23,
                                       unsigned& lo01, unsigned& lo23) {
    asm("cvt.rn.bf16x2.f32 %0, %1, %2;" : "=r"(hi01) : "f"(v.y), "f"(v.x));
    asm("cvt.rn.bf16x2.f32 %0, %1, %2;" : "=r"(hi23) : "f"(v.w), "f"(v.z));
    float h0 = __uint_as_float(hi01 << 16);
    float h1 = __uint_as_float(hi01 & 0xffff0000u);
    float h2 = __uint_as_float(hi23 << 16);
    float h3 = __uint_as_float(hi23 & 0xffff0000u);
    asm("cvt.rn.bf16x2.f32 %0, %1, %2;" : "=r"(lo01) : "f"(v.y - h1), "f"(v.x - h0));
    asm("cvt.rn.bf16x2.f32 %0, %1, %2;" : "=r"(lo23) : "f"(v.w - h3), "f"(v.z - h2));
}

// ---------------------------------------------------------------------------
// Kernel 1 v6: MANY SMALL BLOCKS. 32m x 64n tiles, 128 threads (4 warps of
// 16m x 32n), single-buffered 24KB static smem -> ~8-9 blocks/SM resident.
// Cross-block overlap replaces within-block prefetch; wave quantization
// drops from 2.0x to ~1.3x.
//   rt   0..62 : Ptop rows (dense, clamped at 2000)
//   rt  63..125: Pbot rows [0,2000) (dense, clamped)
//   rt 126..189: P_t rows = embed[t[.]] (gathered)
// ---------------------------------------------------------------------------
#define G1_GRID 380    // 190 row-tiles x 2 n-halves

__global__ void __launch_bounds__(128) gemm1_mma_kernel(const float* __restrict__ embed,
                                                        const int* __restrict__ t) {
    __shared__ char sm[24576];
    __shared__ int t_s[32];
    const unsigned sb = smem_u32(sm);
    const unsigned AHI = 0, ALO = 4096, BHI = 8192, BLO = 16384;
    const int tid = threadIdx.x;
    const int wid = tid >> 5;
    const int lane = tid & 31;

    int bx = blockIdx.x;
    const int nh = bx & 1;
    int rt = bx >> 1;              // 0..189
    int woff, row0, M;
    float* P;
    bool gat = false;
    if (rt < 63)       { woff = 0;     P = g_Ptop; row0 = rt * 32;         M = N_DRUG; }
    else if (rt < 126) { woff = D_DIM; P = g_Pbot; row0 = (rt - 63) * 32;  M = N_DRUG; }
    else { woff = D_DIM; P = g_Pbot + 2000 * H1_DIM; row0 = (rt - 126) * 32; M = B_DIM; gat = true; }
    const int n0 = nh * 64;

    if (gat && tid < 32) t_s[tid] = t[row0 + tid];
    __syncthreads();

    const int m0  = (wid >> 1) * 16;    // 0 or 16
    const int nbw = (wid & 1) * 32;     // 0 or 32

    // staging coords
    const int arow = tid >> 2;              // 0..31
    const int acol = (tid & 3) << 4;        // 0,16,32,48
    const int ag = gat ? t_s[arow] : min(row0 + arow, N_DRUG - 1);
    const float* aptr = embed + (size_t)ag * D_DIM + acol;
    const int brow = tid >> 1;              // 0..63 (n)
    const int bk0  = (tid & 1) * 32;        // k half base
    const __nv_bfloat16* bhp = g_Wthi + (n0 + brow) * 1024 + woff + bk0;
    const __nv_bfloat16* blp = g_Wtlo + (n0 + brow) * 1024 + woff + bk0;

    float acc[4][4];
#pragma unroll
    for (int i = 0; i < 4; i++)
#pragma unroll
        for (int q = 0; q < 4; q++) acc[i][q] = 0.f;

    for (int c = 0; c < 8; c++) {
        const int kb = c * 64;
        // ---- stage A: 32 rows x 64 k, 4 float4 per thread ----
#pragma unroll
        for (int g = 0; g < 4; g++) {
            float4 v = *(const float4*)(aptr + kb + g * 4);
            unsigned hi01, hi23, lo01, lo23;
            split4(v, hi01, hi23, lo01, lo23);
            unsigned off = SW128((unsigned)(arow * 128 + (acol + g * 4) * 2));
            *(uint2*)(sm + AHI + off) = make_uint2(hi01, hi23);
            *(uint2*)(sm + ALO + off) = make_uint2(lo01, lo23);
        }
        // ---- stage B: 64 n x 64 k hi/lo, uint4 (8 bf16) x4 per thread ----
#pragma unroll
        for (int g = 0; g < 4; g++) {
            unsigned off = SW128((unsigned)(brow * 128 + (bk0 + g * 8) * 2));
            *(uint4*)(sm + BHI + off) = *(const uint4*)(bhp + kb + g * 8);
            *(uint4*)(sm + BLO + off) = *(const uint4*)(blp + kb + g * 8);
        }
        __syncthreads();

        // ---- compute: 4 k16 steps ----
#pragma unroll
        for (int ks = 0; ks < 4; ks++) {
            const int k0 = ks * 16;
            unsigned bh[4][2], bl[4][2], t0, t1, t2, t3;
            ldm_x4(bmat_addr(sb + BHI, nbw,      k0, lane), t0, t1, t2, t3);
            bh[0][0] = t0; bh[0][1] = t1; bh[1][0] = t2; bh[1][1] = t3;
            ldm_x4(bmat_addr(sb + BHI, nbw + 16, k0, lane), t0, t1, t2, t3);
            bh[2][0] = t0; bh[2][1] = t1; bh[3][0] = t2; bh[3][1] = t3;
            ldm_x4(bmat_addr(sb + BLO, nbw,      k0, lane), t0, t1, t2, t3);
            bl[0][0] = t0; bl[0][1] = t1; bl[1][0] = t2; bl[1][1] = t3;
            ldm_x4(bmat_addr(sb + BLO, nbw + 16, k0, lane), t0, t1, t2, t3);
            bl[2][0] = t0; bl[2][1] = t1; bl[3][0] = t2; bl[3][1] = t3;
            unsigned ah0, ah1, ah2, ah3, al0, al1, al2, al3;
            ldm_x4(amat_addr(sb + AHI, m0, k0, lane), ah0, ah1, ah2, ah3);
            ldm_x4(amat_addr(sb + ALO, m0, k0, lane), al0, al1, al2, al3);
#pragma unroll
            for (int nf = 0; nf < 4; nf++)
                mma_bf16(acc[nf], ah0, ah1, ah2, ah3, bh[nf][0], bh[nf][1]);
#pragma unroll
            for (int nf = 0; nf < 4; nf++)
                mma_bf16(acc[nf], ah0, ah1, ah2, ah3, bl[nf][0], bl[nf][1]);
#pragma unroll
            for (int nf = 0; nf < 4; nf++)
                mma_bf16(acc[nf], al0, al1, al2, al3, bh[nf][0], bh[nf][1]);
        }
        __syncthreads();
    }

    // ---- epilogue ----
#pragma unroll
    for (int nf = 0; nf < 4; nf++) {
        int r = row0 + m0 + (lane >> 2);
        int col = n0 + nbw + nf * 8 + 2 * (lane & 3);
        if (r < M)
            *(float2*)&P[(size_t)r * H1_DIM + col] = make_float2(acc[nf][0], acc[nf][1]);
        if (r + 8 < M)
            *(float2*)&P[(size_t)(r + 8) * H1_DIM + col] = make_float2(acc[nf][2], acc[nf][3]);
    }
}

// ---------------------------------------------------------------------------
// Kernel 2 (R14, measured 34.7us — FROZEN): 64 samples/block, 3 blocks/SM.
// ---------------------------------------------------------------------------
#define M2_XHI 0
#define M2_XLO 16384
#define M2_WHI 32768
#define M2_WLO 49152
#define M2_MISC 65536
#define M2_SMEM (M2_MISC + (128 + 64 + 64 + 128) * 4 + 3 * 64 * 4)

__global__ void __launch_bounds__(256, 3) mlp2_mma_kernel(
    const int* __restrict__ h, const int* __restrict__ t, const int* __restrict__ ns,
    const float* __restrict__ b1, const float* __restrict__ b2,
    const float* __restrict__ W3, const float* __restrict__ b3,
    float* __restrict__ out)
{
    extern __shared__ char sm[];
    const unsigned sb = smem_u32(sm);
    float* b1s     = (float*)(sm + M2_MISC);
    float* b2s     = b1s + 128;
    float* W3s     = b2s + 64;
    float* partial = W3s + 64;
    int* sTop = (int*)(partial + 128);
    int* sBot = sTop + 64;
    int* sOut = sBot + 64;

    const int tid = threadIdx.x;
    const int wid = tid >> 5;
    const int lane = tid & 31;

    if (tid < 64) {
        int S = blockIdx.x * 64 + tid;
        int b = S / 65;
        int r = S - b * 65;
        int itop, jbot, oaddr;
        if (r == 64)      { itop = h[b];           jbot = 2000 + b;       oaddr = b; }
        else if (r < 32)  { itop = h[b];           jbot = ns[b * 64 + r]; oaddr = B_DIM + b * 64 + r; }
        else              { itop = ns[b * 64 + r]; jbot = 2000 + b;       oaddr = B_DIM + b * 64 + r; }
        sTop[tid] = itop; sBot[tid] = jbot; sOut[tid] = oaddr;
    }
    if (tid < 128) b1s[tid] = b1[tid];
    if (tid < 64) { b2s[tid] = b2[tid]; W3s[tid] = W3[tid]; }
#pragma unroll
    for (int it = 0; it < 8; it++) {
        int idx = it * 256 + tid;
        int c = idx >> 10;
        int rem = idx & 1023;
        int n = rem >> 4;
        int kq = rem & 15;
        unsigned off = (unsigned)(c * 8192) + SW128((unsigned)(n * 128 + kq * 8));
        *(uint2*)(sm + M2_WHI + off) = *(const uint2*)&g_W2thi[n * H1_DIM + c * 64 + kq * 4];
        *(uint2*)(sm + M2_WLO + off) = *(const uint2*)&g_W2tlo[n * H1_DIM + c * 64 + kq * 4];
    }
    __syncthreads();

    {
        const int kcol = lane * 4;
        const int cch = lane >> 4;
        const int kin = (lane & 15) * 4;
        const float4 vb = *(const float4*)&b1s[kcol];
#pragma unroll
        for (int it = 0; it < 8; it++) {
            int s = it * 8 + wid;
            const float* pt = g_Ptop + (size_t)sTop[s] * H1_DIM;
            const float* pb = g_Pbot + (size_t)sBot[s] * H1_DIM;
            float4 pa = *(const float4*)&pt[kcol];
            float4 pv = *(const float4*)&pb[kcol];
            float4 x;
            x.x = fmaxf(pa.x + pv.x + vb.x, 0.f);
            x.y = fmaxf(pa.y + pv.y + vb.y, 0.f);
            x.z = fmaxf(pa.z + pv.z + vb.z, 0.f);
            x.w = fmaxf(pa.w + pv.w + vb.w, 0.f);
            unsigned hi01, hi23, lo01, lo23;
            split4(x, hi01, hi23, lo01, lo23);
            unsigned off = (unsigned)(cch * 8192) + SW128((unsigned)(s * 128 + kin * 2));
            *(uint2*)(sm + M2_XHI + off) = make_uint2(hi01, hi23);
            *(uint2*)(sm + M2_XLO + off) = make_uint2(lo01, lo23);
        }
    }
    __syncthreads();

    const int m0 = (wid >> 1) * 16;
    const int wn = wid & 1;
    const int nb = wn * 32;

    float acc[4][4];
#pragma unroll
    for (int j = 0; j < 4; j++)
#pragma unroll
        for (int q = 0; q < 4; q++) acc[j][q] = 0.f;

#pragma unroll
    for (int c = 0; c < 2; c++) {
        const unsigned xbhi = sb + M2_XHI + c * 8192;
        const unsigned xblo = sb + M2_XLO + c * 8192;
        const unsigned wbhi = sb + M2_WHI + c * 8192;
        const unsigned wblo = sb + M2_WLO + c * 8192;
#pragma unroll
        for (int ks = 0; ks < 4; ks++) {
            const int k0 = ks * 16;
            unsigned bh[4][2], bl[4][2], t0, t1, t2, t3;
            ldm_x4(bmat_addr(wbhi, nb,      k0, lane), t0, t1, t2, t3);
            bh[0][0] = t0; bh[0][1] = t1; bh[1][0] = t2; bh[1][1] = t3;
            ldm_x4(bmat_addr(wbhi, nb + 16, k0, lane), t0, t1, t2, t3);
            bh[2][0] = t0; bh[2][1] = t1; bh[3][0] = t2; bh[3][1] = t3;
            ldm_x4(bmat_addr(wblo, nb,      k0, lane), t0, t1, t2, t3);
            bl[0][0] = t0; bl[0][1] = t1; bl[1][0] = t2; bl[1][1] = t3;
            ldm_x4(bmat_addr(wblo, nb + 16, k0, lane), t0, t1, t2, t3);
            bl[2][0] = t0; bl[2][1] = t1; bl[3][0] = t2; bl[3][1] = t3;
            unsigned ah0, ah1, ah2, ah3, al0, al1, al2, al3;
            ldm_x4(amat_addr(xbhi, m0, k0, lane), ah0, ah1, ah2, ah3);
            ldm_x4(amat_addr(xblo, m0, k0, lane), al0, al1, al2, al3);
#pragma unroll
            for (int nf = 0; nf < 4; nf++)
                mma_bf16(acc[nf], ah0, ah1, ah2, ah3, bh[nf][0], bh[nf][1]);
#pragma unroll
            for (int nf = 0; nf < 4; nf++)
                mma_bf16(acc[nf], ah0, ah1, ah2, ah3, bl[nf][0], bl[nf][1]);
#pragma unroll
            for (int nf = 0; nf < 4; nf++)
                mma_bf16(acc[nf], al0, al1, al2, al3, bh[nf][0], bh[nf][1]);
        }
    }

    {
        float p0 = 0.f, p8 = 0.f;
#pragma unroll
        for (int nf = 0; nf < 4; nf++) {
            int n0i = nb + nf * 8 + 2 * (lane & 3);
            float b20 = b2s[n0i], b21 = b2s[n0i + 1];
            float w30 = W3s[n0i], w31 = W3s[n0i + 1];
            p0 = fmaf(fmaxf(acc[nf][0] + b20, 0.f), w30, p0);
            p0 = fmaf(fmaxf(acc[nf][1] + b21, 0.f), w31, p0);
            p8 = fmaf(fmaxf(acc[nf][2] + b20, 0.f), w30, p8);
            p8 = fmaf(fmaxf(acc[nf][3] + b21, 0.f), w31, p8);
        }
        p0 += __shfl_xor_sync(0xffffffffu, p0, 1);
        p0 += __shfl_xor_sync(0xffffffffu, p0, 2);
        p8 += __shfl_xor_sync(0xffffffffu, p8, 1);
        p8 += __shfl_xor_sync(0xffffffffu, p8, 2);
        if ((lane & 3) == 0) {
            int r = m0 + (lane >> 2);
            partial[r * 2 + wn]       = p0;
            partial[(r + 8) * 2 + wn] = p8;
        }
    }
    __syncthreads();
    if (tid < 64)
        out[sOut[tid]] = partial[tid * 2] + partial[tid * 2 + 1] + b3[0];
}

// ---------------------------------------------------------------------------
extern "C" void kernel_launch(void* const* d_in, const int* in_sizes, int n_in,
                              void* d_out, int out_size) {
    const float* embed = (const float*)d_in[0];
    const float* W1    = (const float*)d_in[1];
    const float* b1    = (const float*)d_in[2];
    const float* W2    = (const float*)d_in[3];
    const float* b2    = (const float*)d_in[4];
    const float* W3    = (const float*)d_in[5];
    const float* b3    = (const float*)d_in[6];
    const int*   h     = (const int*)d_in[7];
    const int*   t     = (const int*)d_in[8];
    const int*   ns    = (const int*)d_in[9];
    float* out = (float*)d_out;

    convert_w1_kernel<<<32, 256>>>(W1);
    convert_w2_kernel<<<32, 256>>>(W2);

    gemm1_mma_kernel<<<G1_GRID, 128>>>(embed, t);

    cudaFuncSetAttribute(mlp2_mma_kernel, cudaFuncAttributeMaxDynamicSharedMemorySize,
                         M2_SMEM);
    mlp2_mma_kernel<<<(B_DIM * 65) / 64, 256, M2_SMEM>>>(h, t, ns, b1, b2, W3, b3, out);
}